// round 11
// baseline (speedup 1.0000x reference)
#include <cuda_runtime.h>
#include <cuda_bf16.h>
#include <cstdint>
#include <cstddef>

// Problem constants
#define NB 8
#define NH 12
#define SQ 1024
#define DH 64
#define EMB 768
#define BHC (NB*NH)      // 96
#define ACT_N (NB*SQ*EMB)   // 6291456
#define WN (EMB*EMB)        // 589824

// ---------------- scratch (static device globals; no allocation) ----------------
__device__ __nv_bfloat16 g_lh [ACT_N], g_ll [ACT_N];
__device__ __nv_bfloat16 g_sph[ACT_N], g_spl[ACT_N];
__device__ __nv_bfloat16 g_pph[ACT_N], g_ppl[ACT_N];
__device__ __nv_bfloat16 g_Wh [5*WN],  g_Wl [5*WN];     // Wq,Wksp,Wkp,Wvsp,Wo
__device__ __nv_bfloat16 g_qh  [ACT_N], g_ql  [ACT_N];
__device__ __nv_bfloat16 g_ksph[ACT_N], g_kspl[ACT_N];
__device__ __nv_bfloat16 g_kph [ACT_N], g_kpl [ACT_N];
__device__ __nv_bfloat16 g_vTh [ACT_N], g_vTl [ACT_N];  // [b,h,d,s]
__device__ float g_A1 [100663296];                // [bh][k][s]
__device__ float g_A2 [100663296];                // [bh][p][s]
__device__ __nv_bfloat16 g_A1h[100663296], g_A2h[100663296];
__device__ float g_SP [100663296];                // [bh][p][k]
__device__ __nv_bfloat16 g_SPh[100663296], g_SPl[100663296];
__device__ __nv_bfloat16 g_ctxh[ACT_N], g_ctxl[ACT_N];  // [b,p,e]

// =====================  helpers (baseline ISA only — no 'a' features) =====
__device__ __forceinline__ uint32_t smem_to_u32(const void* p) {
    uint32_t a;
    asm("{ .reg .u64 t; cvta.to.shared.u64 t, %1; cvt.u32.u64 %0, t; }" : "=r"(a) : "l"(p));
    return a;
}
__device__ __forceinline__ void cp_async16(uint32_t saddr, const void* gaddr) {
    asm volatile("cp.async.cg.shared.global [%0], [%1], 16;\n" :: "r"(saddr), "l"(gaddr));
}
#define CP_COMMIT()  asm volatile("cp.async.commit_group;\n" ::: "memory")
#define CP_WAIT(n)   asm volatile("cp.async.wait_group %0;\n" :: "n"(n) : "memory")
#define SWZ64(o) ((o) ^ (((o) >> 3) & 0x30))

__device__ __forceinline__ void ldmatrix_x4(uint32_t* r, uint32_t addr) {
    asm volatile("ldmatrix.sync.aligned.m8n8.x4.shared.b16 {%0,%1,%2,%3}, [%4];"
        : "=r"(r[0]), "=r"(r[1]), "=r"(r[2]), "=r"(r[3]) : "r"(addr));
}
__device__ __forceinline__ void mma16816(float* c, const uint32_t* a, uint32_t b0, uint32_t b1) {
    asm volatile("mma.sync.aligned.m16n8k16.row.col.f32.bf16.bf16.f32 "
        "{%0,%1,%2,%3}, {%4,%5,%6,%7}, {%8,%9}, {%0,%1,%2,%3};"
        : "+f"(c[0]), "+f"(c[1]), "+f"(c[2]), "+f"(c[3])
        : "r"(a[0]), "r"(a[1]), "r"(a[2]), "r"(a[3]), "r"(b0), "r"(b1));
}
__device__ __forceinline__ void split1(float v, __nv_bfloat16& h, __nv_bfloat16& l) {
    h = __float2bfloat16(v);
    l = __float2bfloat16(v - __bfloat162float(h));
}

// =================================================================================
// Unified bf16 NT GEMM: C[m,n] = sum over segments of sum_k Aseg[m,k]*Bseg[n,k].
// CTA tile 128(m) x BN(n), BK=32 (64B swizzled rows), 3-stage cp.async pipeline.
// 8 warps (2 x m) x (4 x n); warp tile 64 x (BN/4); mma.sync m16n8k16 bf16.
// Segments (up to 3): (A_hi,B_hi), (A_lo,B_hi), (A_hi,B_lo)  [fp32-split trick]
// Epilogues:
//  0: fp32 store  Cf[z*sC + m*ldc + n]
//  1: (acc+bias[e])*alpha -> hi/lo bf16 head layout [b,h,s,d]
//  2: same but transposed head layout [b,h,d,s]
//  3: acc -> hi/lo bf16 ctx layout [b, p, h*64+d]
//  4: acc+bias[n] -> fp32 out[m*EMB + n]
// =================================================================================
template<int EPI, int BN>
__global__ void __launch_bounds__(256)
gemm_bf16nt(const __nv_bfloat16* __restrict__ A0, const __nv_bfloat16* __restrict__ A1p,
            const __nv_bfloat16* __restrict__ A2p,
            const __nv_bfloat16* __restrict__ B0, const __nv_bfloat16* __restrict__ B1p,
            const __nv_bfloat16* __restrict__ B2p,
            int nseg, int K, size_t sA, size_t sB,
            float* __restrict__ Cf, __nv_bfloat16* __restrict__ Chi,
            __nv_bfloat16* __restrict__ Clo,
            const float* __restrict__ bias, float alpha, int ldc, size_t sC)
{
    constexpr int STRIDE = 8192 + BN * 64;          // A(8KB) + B(BN*64B) per stage
    constexpr int NN8 = BN / 32;                    // n8 blocks per warp (4 or 2)
    constexpr int NB16 = BN / 64;                   // n16 ldmatrix tiles per warp (2 or 1)
    __shared__ __align__(1024) char smem_buf[3 * STRIDE];
    const uint32_t sb = smem_to_u32(smem_buf);
    const int tid = threadIdx.x, wid = tid >> 5, lane = tid & 31;
    const int z = blockIdx.z;
    const int m0 = blockIdx.y * 128, n0 = blockIdx.x * BN;
    const int cps = K >> 5;                         // 32-elem chunks per segment

    int l_seg = 0, l_kc = 0, l_t = 0;               // in-order load cursor
    auto load_chunk = [&]() {
        const __nv_bfloat16* Ab = (l_seg == 0) ? A0 : ((l_seg == 1) ? A1p : A2p);
        const __nv_bfloat16* Bb = (l_seg == 0) ? B0 : ((l_seg == 1) ? B1p : B2p);
        Ab += (size_t)z * sA + (size_t)m0 * K + l_kc * 32;
        Bb += (size_t)z * sB + (size_t)n0 * K + l_kc * 32;
        uint32_t bA = sb + (uint32_t)((l_t % 3) * STRIDE);
        uint32_t bB = bA + 8192u;
        #pragma unroll
        for (int i = 0; i < 2; i++) {               // A: 128 rows x 4 x 16B
            int u = tid + i * 256, r = u >> 2, c = u & 3;
            cp_async16(bA + SWZ64((uint32_t)(r * 64 + c * 16)), Ab + (size_t)r * K + c * 8);
        }
        #pragma unroll
        for (int i = 0; i < BN / 64; i++) {         // B: BN rows x 4 x 16B
            int u = tid + i * 256, r = u >> 2, c = u & 3;
            cp_async16(bB + SWZ64((uint32_t)(r * 64 + c * 16)), Bb + (size_t)r * K + c * 8);
        }
        CP_COMMIT();
        ++l_t;
        if (++l_kc == cps) { l_kc = 0; ++l_seg; }
    };

    const int T = nseg * cps;
    load_chunk();
    load_chunk();

    const int wm = (wid & 1) * 64;                  // warp m offset (0/64)
    const int wn = (wid >> 1) * (BN / 4);           // warp n offset
    const int lg = lane >> 3;
    const int lr = lane & 7;

    float acc[4][NN8][4];
    #pragma unroll
    for (int im = 0; im < 4; im++)
        #pragma unroll
        for (int in = 0; in < NN8; in++)
            #pragma unroll
            for (int r = 0; r < 4; r++) acc[im][in][r] = 0.f;

    #pragma unroll 1
    for (int t = 0; t < T; t++) {
        CP_WAIT(1);                                 // chunk t resident
        __syncthreads();                            // all warps past compute(t-1)
        if (t + 2 < T) load_chunk();                // refill buffer (t+2)%3 == (t-1)%3
        uint32_t bA = sb + (uint32_t)((t % 3) * STRIDE);
        uint32_t bB = bA + 8192u;

        #pragma unroll
        for (int ks = 0; ks < 2; ks++) {
            const int kb = ks * 32 + (lg >> 1) * 16;
            uint32_t a[4][4], b[NB16][4];
            #pragma unroll
            for (int im = 0; im < 4; im++) {
                int row = wm + im * 16 + (lg & 1) * 8 + lr;
                ldmatrix_x4(a[im], bA + SWZ64((uint32_t)(row * 64 + kb)));
            }
            #pragma unroll
            for (int ib = 0; ib < NB16; ib++) {
                int row = wn + ib * 16 + (lg & 1) * 8 + lr;
                ldmatrix_x4(b[ib], bB + SWZ64((uint32_t)(row * 64 + kb)));
            }
            #pragma unroll
            for (int im = 0; im < 4; im++)
                #pragma unroll
                for (int in = 0; in < NN8; in++) {
                    int ib = in >> 1, hi = in & 1;
                    mma16816(acc[im][in], a[im], b[ib][hi], b[ib][2 + hi]);
                }
        }
    }

    // ---------------- epilogue ----------------
    #pragma unroll
    for (int im = 0; im < 4; im++)
        #pragma unroll
        for (int half = 0; half < 2; half++) {
            int m = wm + im * 16 + (lane >> 2) + half * 8;   // local m
            #pragma unroll
            for (int in = 0; in < NN8; in++) {
                int n = wn + in * 8 + (lane & 3) * 2;        // local n (even)
                float v0 = acc[im][in][half * 2 + 0];
                float v1 = acc[im][in][half * 2 + 1];

                if (EPI == 0) {
                    *(float2*)(Cf + (size_t)z * sC + (size_t)(m0 + m) * ldc + n0 + n) =
                        make_float2(v0, v1);
                } else if (EPI == 1 || EPI == 2) {
                    int e = n0 + n, mg = m0 + m;
                    v0 = (v0 + bias[e]) * alpha;
                    v1 = (v1 + bias[e + 1]) * alpha;
                    int b = mg >> 10, s = mg & 1023, h = e >> 6, d = e & 63;
                    __nv_bfloat16 h0, l0, h1, l1;
                    split1(v0, h0, l0); split1(v1, h1, l1);
                    if (EPI == 1) {
                        size_t idx = (((size_t)(b * NH + h)) * SQ + s) * DH + d;
                        __nv_bfloat162 hp; hp.x = h0; hp.y = h1;
                        __nv_bfloat162 lp; lp.x = l0; lp.y = l1;
                        *(__nv_bfloat162*)(Chi + idx) = hp;
                        *(__nv_bfloat162*)(Clo + idx) = lp;
                    } else {
                        size_t base = (((size_t)(b * NH + h)) * DH + d) * SQ + s;
                        Chi[base] = h0;      Clo[base] = l0;
                        Chi[base + SQ] = h1; Clo[base + SQ] = l1;
                    }
                } else if (EPI == 3) {
                    int b = z / NH, h = z - b * NH;
                    int p = m0 + m;
                    size_t idx = ((size_t)(b * SQ + p)) * EMB + h * DH + (n0 + n);
                    __nv_bfloat16 h0, l0, h1, l1;
                    split1(v0, h0, l0); split1(v1, h1, l1);
                    __nv_bfloat162 hp; hp.x = h0; hp.y = h1;
                    __nv_bfloat162 lp; lp.x = l0; lp.y = l1;
                    *(__nv_bfloat162*)(Chi + idx) = hp;
                    *(__nv_bfloat162*)(Clo + idx) = lp;
                } else {  // EPI == 4
                    int e = n0 + n;
                    *(float2*)(Cf + (size_t)(m0 + m) * EMB + e) =
                        make_float2(v0 + bias[e], v1 + bias[e + 1]);
                }
            }
        }
}

// =================================================================================
// fp32 -> (hi, lo) bf16 split, elementwise
// =================================================================================
__global__ void __launch_bounds__(256)
split_pair(const float* __restrict__ x, __nv_bfloat16* __restrict__ hi,
           __nv_bfloat16* __restrict__ lo, int n)
{
    int i = blockIdx.x * 256 + threadIdx.x;
    if (i * 4 >= n) return;
    float4 v = ((const float4*)x)[i];
    __nv_bfloat16 h0, l0, h1, l1, h2, l2, h3, l3;
    split1(v.x, h0, l0); split1(v.y, h1, l1);
    split1(v.z, h2, l2); split1(v.w, h3, l3);
    __nv_bfloat162 ha, hb, la, lb;
    ha.x = h0; ha.y = h1; hb.x = h2; hb.y = h3;
    la.x = l0; la.y = l1; lb.x = l2; lb.y = l3;
    ((__nv_bfloat162*)hi)[2 * i]     = ha;
    ((__nv_bfloat162*)hi)[2 * i + 1] = hb;
    ((__nv_bfloat162*)lo)[2 * i]     = la;
    ((__nv_bfloat162*)lo)[2 * i + 1] = lb;
}

// =================================================================================
// Row softmax over rows of length 1024 (contiguous).
// =================================================================================
__device__ __forceinline__ float4 softmax_core(float4 v, int t, float* red) {
    float m = fmaxf(fmaxf(v.x, v.y), fmaxf(v.z, v.w));
    #pragma unroll
    for (int o = 16; o; o >>= 1) m = fmaxf(m, __shfl_xor_sync(0xffffffffu, m, o));
    if ((t & 31) == 0) red[t >> 5] = m;
    __syncthreads();
    m = red[0];
    #pragma unroll
    for (int i = 1; i < 8; i++) m = fmaxf(m, red[i]);

    v.x = __expf(v.x - m); v.y = __expf(v.y - m);
    v.z = __expf(v.z - m); v.w = __expf(v.w - m);
    float s = v.x + v.y + v.z + v.w;
    #pragma unroll
    for (int o = 16; o; o >>= 1) s += __shfl_xor_sync(0xffffffffu, s, o);
    __syncthreads();
    if ((t & 31) == 0) red[t >> 5] = s;
    __syncthreads();
    s = red[0];
    #pragma unroll
    for (int i = 1; i < 8; i++) s += red[i];

    float inv = 1.0f / s;
    v.x *= inv; v.y *= inv; v.z *= inv; v.w *= inv;
    return v;
}

__global__ void __launch_bounds__(256)
softmax_rows_bf16(const float* __restrict__ in, __nv_bfloat16* __restrict__ out)
{
    const float* rowp = in + (size_t)blockIdx.x * 1024;
    __nv_bfloat16* orow = out + (size_t)blockIdx.x * 1024;
    const int t = threadIdx.x;
    __shared__ float red[8];
    float4 v = ((float4*)rowp)[t];
    v = softmax_core(v, t, red);
    __nv_bfloat162 p0, p1;
    p0.x = __float2bfloat16(v.x); p0.y = __float2bfloat16(v.y);
    p1.x = __float2bfloat16(v.z); p1.y = __float2bfloat16(v.w);
    ((__nv_bfloat162*)orow)[2 * t]     = p0;
    ((__nv_bfloat162*)orow)[2 * t + 1] = p1;
}

__global__ void __launch_bounds__(256)
softmax_rows_split(const float* __restrict__ in, __nv_bfloat16* __restrict__ hi,
                   __nv_bfloat16* __restrict__ lo)
{
    const float* rowp = in + (size_t)blockIdx.x * 1024;
    __nv_bfloat16* hrow = hi + (size_t)blockIdx.x * 1024;
    __nv_bfloat16* lrow = lo + (size_t)blockIdx.x * 1024;
    const int t = threadIdx.x;
    __shared__ float red[8];
    float4 v = ((float4*)rowp)[t];
    v = softmax_core(v, t, red);
    __nv_bfloat16 h0, l0, h1, l1, h2, l2, h3, l3;
    split1(v.x, h0, l0); split1(v.y, h1, l1);
    split1(v.z, h2, l2); split1(v.w, h3, l3);
    __nv_bfloat162 ha, hb, la, lb;
    ha.x = h0; ha.y = h1; hb.x = h2; hb.y = h3;
    la.x = l0; la.y = l1; lb.x = l2; lb.y = l3;
    ((__nv_bfloat162*)hrow)[2 * t]     = ha;
    ((__nv_bfloat162*)hrow)[2 * t + 1] = hb;
    ((__nv_bfloat162*)lrow)[2 * t]     = la;
    ((__nv_bfloat162*)lrow)[2 * t + 1] = lb;
}

// =================================================================================
extern "C" void kernel_launch(void* const* d_in, const int* in_sizes, int n_in,
                              void* d_out, int out_size)
{
    const float* l    = (const float*)d_in[0];
    const float* sp   = (const float*)d_in[1];
    const float* pp   = (const float*)d_in[2];
    const float* Wq   = (const float*)d_in[3];
    const float* bq   = (const float*)d_in[4];
    const float* Wksp = (const float*)d_in[5];
    const float* bksp = (const float*)d_in[6];
    const float* Wkp  = (const float*)d_in[7];
    const float* bkp  = (const float*)d_in[8];
    const float* Wvsp = (const float*)d_in[9];
    const float* bvsp = (const float*)d_in[10];
    const float* Wo   = (const float*)d_in[13];
    const float* bo   = (const float*)d_in[14];
    float* out = (float*)d_out;

    __nv_bfloat16 *lh, *ll, *sph, *spl, *pph, *ppl, *Wh, *Wl;
    __nv_bfloat16 *qh, *ql, *ksph, *kspl, *kph, *kpl, *vTh, *vTl;
    __nv_bfloat16 *A1h, *A2h, *SPh, *SPl, *ctxh, *ctxl;
    float *A1, *A2, *SP;
    cudaGetSymbolAddress((void**)&lh,  g_lh);   cudaGetSymbolAddress((void**)&ll,  g_ll);
    cudaGetSymbolAddress((void**)&sph, g_sph);  cudaGetSymbolAddress((void**)&spl, g_spl);
    cudaGetSymbolAddress((void**)&pph, g_pph);  cudaGetSymbolAddress((void**)&ppl, g_ppl);
    cudaGetSymbolAddress((void**)&Wh,  g_Wh);   cudaGetSymbolAddress((void**)&Wl,  g_Wl);
    cudaGetSymbolAddress((void**)&qh,  g_qh);   cudaGetSymbolAddress((void**)&ql,  g_ql);
    cudaGetSymbolAddress((void**)&ksph, g_ksph); cudaGetSymbolAddress((void**)&kspl, g_kspl);
    cudaGetSymbolAddress((void**)&kph, g_kph);  cudaGetSymbolAddress((void**)&kpl, g_kpl);
    cudaGetSymbolAddress((void**)&vTh, g_vTh);  cudaGetSymbolAddress((void**)&vTl, g_vTl);
    cudaGetSymbolAddress((void**)&A1,  g_A1);   cudaGetSymbolAddress((void**)&A2,  g_A2);
    cudaGetSymbolAddress((void**)&A1h, g_A1h);  cudaGetSymbolAddress((void**)&A2h, g_A2h);
    cudaGetSymbolAddress((void**)&SP,  g_SP);
    cudaGetSymbolAddress((void**)&SPh, g_SPh);  cudaGetSymbolAddress((void**)&SPl, g_SPl);
    cudaGetSymbolAddress((void**)&ctxh, g_ctxh); cudaGetSymbolAddress((void**)&ctxl, g_ctxl);

    const float scale = 0.125f;  // 64^-0.5
    const size_t sHead = (size_t)SQ * DH;    // 65536
    const size_t sMat  = (size_t)SQ * SQ;    // 1048576

    // ---- split inputs to (hi, lo) bf16 ----
    split_pair<<<ACT_N / 1024, 256>>>(l,  lh,  ll,  ACT_N);
    split_pair<<<ACT_N / 1024, 256>>>(sp, sph, spl, ACT_N);
    split_pair<<<ACT_N / 1024, 256>>>(pp, pph, ppl, ACT_N);
    split_pair<<<WN / 1024, 256>>>(Wq,   Wh + 0 * WN, Wl + 0 * WN, WN);
    split_pair<<<WN / 1024, 256>>>(Wksp, Wh + 1 * WN, Wl + 1 * WN, WN);
    split_pair<<<WN / 1024, 256>>>(Wkp,  Wh + 2 * WN, Wl + 2 * WN, WN);
    split_pair<<<WN / 1024, 256>>>(Wvsp, Wh + 3 * WN, Wl + 3 * WN, WN);
    split_pair<<<WN / 1024, 256>>>(Wo,   Wh + 4 * WN, Wl + 4 * WN, WN);

    // ---- projections (split bf16, 3 segments) ----
    dim3 gProj(EMB / 128, (NB * SQ) / 128, 1);   // (6, 64)
    gemm_bf16nt<1,128><<<gProj, 256>>>(lh,  ll,  lh,  Wh + 0*WN, Wh + 0*WN, Wl + 0*WN,
                                       3, EMB, 0, 0, nullptr, qh,  ql,  bq,   scale, 0, 0);
    gemm_bf16nt<1,128><<<gProj, 256>>>(sph, spl, sph, Wh + 1*WN, Wh + 1*WN, Wl + 1*WN,
                                       3, EMB, 0, 0, nullptr, ksph, kspl, bksp, scale, 0, 0);
    gemm_bf16nt<1,128><<<gProj, 256>>>(pph, ppl, pph, Wh + 2*WN, Wh + 2*WN, Wl + 2*WN,
                                       3, EMB, 0, 0, nullptr, kph, kpl, bkp,  scale, 0, 0);
    gemm_bf16nt<2,128><<<gProj, 256>>>(sph, spl, sph, Wh + 3*WN, Wh + 3*WN, Wl + 3*WN,
                                       3, EMB, 0, 0, nullptr, vTh, vTl, bvsp, scale, 0, 0);

    // ---- transposed logits: A1[k,s] = ksp_k . q_s ; A2[p,s] = kp_p . q_s ----
    dim3 gLog(SQ / 128, SQ / 128, BHC);          // (8, 8, 96)
    gemm_bf16nt<0,128><<<gLog, 256>>>(ksph, kspl, ksph, qh, qh, ql,
                                      3, DH, sHead, sHead, A1, nullptr, nullptr, nullptr, 1.f, SQ, sMat);
    gemm_bf16nt<0,128><<<gLog, 256>>>(kph, kpl, kph, qh, qh, ql,
                                      3, DH, sHead, sHead, A2, nullptr, nullptr, nullptr, 1.f, SQ, sMat);

    // ---- softmax over s (row-wise) -> bf16 ----
    softmax_rows_bf16<<<BHC * SQ, 256>>>(A1, A1h);
    softmax_rows_bf16<<<BHC * SQ, 256>>>(A2, A2h);

    // ---- sp2p[p,k] = sum_s A2[p,s] * A1[k,s]  (single-segment bf16) ----
    gemm_bf16nt<0,128><<<gLog, 256>>>(A2h, A2h, A2h, A1h, A1h, A1h,
                                      1, SQ, sMat, sMat, SP, nullptr, nullptr, nullptr, 1.f, SQ, sMat);

    // ---- softmax over k (row-wise) -> hi/lo split ----
    softmax_rows_split<<<BHC * SQ, 256>>>(SP, SPh, SPl);

    // ---- ctx[b,p,h*64+d] = sum_k SP[p,k] * vsp[k,d]  (split bf16 NT, BN=64) ----
    dim3 gCtx(1, SQ / 128, BHC);                 // (1, 8, 96)
    gemm_bf16nt<3,64><<<gCtx, 256>>>(SPh, SPl, SPh, vTh, vTh, vTl,
                                     3, SQ, sMat, sHead, nullptr, ctxh, ctxl, nullptr, 1.f, 0, 0);

    // ---- final: out = ctx @ Wo^T + bo ----
    gemm_bf16nt<4,128><<<gProj, 256>>>(ctxh, ctxl, ctxh, Wh + 4*WN, Wh + 4*WN, Wl + 4*WN,
                                       3, EMB, 0, 0, out, nullptr, nullptr, bo, 1.f, 0, 0);
}

// round 12
// speedup vs baseline: 1.2125x; 1.2125x over previous
#include <cuda_runtime.h>
#include <cuda_bf16.h>
#include <cstdint>
#include <cstddef>

// Problem constants
#define NB 8
#define NH 12
#define SQ 1024
#define DH 64
#define EMB 768
#define BHC (NB*NH)      // 96
#define ACT_N (NB*SQ*EMB)   // 6291456
#define WN (EMB*EMB)        // 589824

// ---------------- scratch (static device globals; no allocation) ----------------
__device__ __nv_bfloat16 g_lh [ACT_N], g_ll [ACT_N];
__device__ __nv_bfloat16 g_sph[ACT_N], g_spl[ACT_N];
__device__ __nv_bfloat16 g_pph[ACT_N], g_ppl[ACT_N];
__device__ __nv_bfloat16 g_Wh [5*WN],  g_Wl [5*WN];     // Wq,Wksp,Wkp,Wvsp,Wo
__device__ __nv_bfloat16 g_qh  [ACT_N], g_ql  [ACT_N];
__device__ __nv_bfloat16 g_ksph[ACT_N], g_kspl[ACT_N];
__device__ __nv_bfloat16 g_kph [ACT_N], g_kpl [ACT_N];
__device__ __nv_bfloat16 g_vTh [ACT_N], g_vTl [ACT_N];  // [b,h,d,s]
__device__ __nv_bfloat16 g_A1r[100663296], g_A2r[100663296];   // raw logits (bf16)
__device__ __nv_bfloat16 g_A1h[100663296], g_A2h[100663296];   // softmaxed (bf16)
__device__ __nv_bfloat16 g_SPr[100663296];                      // raw sp2p (bf16)
__device__ __nv_bfloat16 g_SPh[100663296], g_SPl[100663296];   // softmaxed hi/lo
__device__ __nv_bfloat16 g_ctxh[ACT_N], g_ctxl[ACT_N];          // [b,p,e]

// =====================  helpers (baseline ISA only — no 'a' features) =====
__device__ __forceinline__ uint32_t smem_to_u32(const void* p) {
    uint32_t a;
    asm("{ .reg .u64 t; cvta.to.shared.u64 t, %1; cvt.u32.u64 %0, t; }" : "=r"(a) : "l"(p));
    return a;
}
__device__ __forceinline__ void cp_async16(uint32_t saddr, const void* gaddr) {
    asm volatile("cp.async.cg.shared.global [%0], [%1], 16;\n" :: "r"(saddr), "l"(gaddr));
}
#define CP_COMMIT()  asm volatile("cp.async.commit_group;\n" ::: "memory")
#define CP_WAIT(n)   asm volatile("cp.async.wait_group %0;\n" :: "n"(n) : "memory")
#define SWZ128(o) ((o) ^ (((o) >> 3) & 0x70))

__device__ __forceinline__ void ldmatrix_x4(uint32_t* r, uint32_t addr) {
    asm volatile("ldmatrix.sync.aligned.m8n8.x4.shared.b16 {%0,%1,%2,%3}, [%4];"
        : "=r"(r[0]), "=r"(r[1]), "=r"(r[2]), "=r"(r[3]) : "r"(addr));
}
__device__ __forceinline__ void mma16816(float* c, const uint32_t* a, uint32_t b0, uint32_t b1) {
    asm volatile("mma.sync.aligned.m16n8k16.row.col.f32.bf16.bf16.f32 "
        "{%0,%1,%2,%3}, {%4,%5,%6,%7}, {%8,%9}, {%0,%1,%2,%3};"
        : "+f"(c[0]), "+f"(c[1]), "+f"(c[2]), "+f"(c[3])
        : "r"(a[0]), "r"(a[1]), "r"(a[2]), "r"(a[3]), "r"(b0), "r"(b1));
}
__device__ __forceinline__ void split1(float v, __nv_bfloat16& h, __nv_bfloat16& l) {
    h = __float2bfloat16(v);
    l = __float2bfloat16(v - __bfloat162float(h));
}

// =================================================================================
// Unified bf16 NT GEMM (R10-proven core): C[m,n] = sum_seg sum_k Aseg[m,k]*Bseg[n,k].
// CTA tile 128(m) x 64(n), BK=64 (128B rows, SW128), double-buffered cp.async.
// 8 warps (4x2), warp tile 32x32, mma.sync m16n8k16 bf16 -> fp32 acc.
// Epilogues:
//  0: fp32 store  Cf[z*sC + m*ldc + n]
//  1: (acc+bias[e])*alpha -> hi/lo bf16 head layout [b,h,s,d]
//  2: same but transposed head layout [b,h,d,s]
//  3: acc -> hi/lo bf16 ctx layout [b, p, h*64+d]
//  4: acc+bias[n] -> fp32 out[m*EMB + n]
//  5: acc -> bf16 store Chi[z*sC + m*ldc + n]
// =================================================================================
template<int EPI>
__global__ void __launch_bounds__(256)
gemm_bf16nt(const __nv_bfloat16* __restrict__ A0, const __nv_bfloat16* __restrict__ A1p,
            const __nv_bfloat16* __restrict__ A2p,
            const __nv_bfloat16* __restrict__ B0, const __nv_bfloat16* __restrict__ B1p,
            const __nv_bfloat16* __restrict__ B2p,
            int nseg, int K, size_t sA, size_t sB,
            float* __restrict__ Cf, __nv_bfloat16* __restrict__ Chi,
            __nv_bfloat16* __restrict__ Clo,
            const float* __restrict__ bias, float alpha, int ldc, size_t sC)
{
    __shared__ __align__(1024) char smem_buf[49152];   // 2 x (16KB A + 8KB B)
    const uint32_t sb = smem_to_u32(smem_buf);
    const int tid = threadIdx.x, wid = tid >> 5, lane = tid & 31;
    const int z = blockIdx.z;
    const int m0 = blockIdx.y * 128, n0 = blockIdx.x * 64;
    const int cps = K >> 6;                  // 64-elem chunks per segment

    int l_seg = 0, l_kc = 0;                 // in-order load cursor
    auto load_chunk = [&](int buf) {
        const __nv_bfloat16* Ab = (l_seg == 0) ? A0 : ((l_seg == 1) ? A1p : A2p);
        const __nv_bfloat16* Bb = (l_seg == 0) ? B0 : ((l_seg == 1) ? B1p : B2p);
        Ab += (size_t)z * sA + (size_t)m0 * K + l_kc * 64;
        Bb += (size_t)z * sB + (size_t)n0 * K + l_kc * 64;
        uint32_t bA = sb + (uint32_t)buf * 24576u;
        uint32_t bB = bA + 16384u;
        #pragma unroll
        for (int i = 0; i < 4; i++) {                 // A: 128 rows x 8 x 16B
            int u = tid + i * 256, r = u >> 3, c = u & 7;
            cp_async16(bA + SWZ128((uint32_t)(r * 128 + c * 16)), Ab + (size_t)r * K + c * 8);
        }
        #pragma unroll
        for (int i = 0; i < 2; i++) {                 // B: 64 rows x 8 x 16B
            int u = tid + i * 256, r = u >> 3, c = u & 7;
            cp_async16(bB + SWZ128((uint32_t)(r * 128 + c * 16)), Bb + (size_t)r * K + c * 8);
        }
        CP_COMMIT();
        if (++l_kc == cps) { l_kc = 0; ++l_seg; }
    };

    const int T = nseg * cps;
    load_chunk(0);
    load_chunk(1);

    const int wm = (wid & 3) * 32;    // warp m offset
    const int wn = (wid >> 2) * 32;   // warp n offset
    const int lg = lane >> 3;
    const int lr = lane & 7;

    float acc[2][4][4];
    #pragma unroll
    for (int im = 0; im < 2; im++)
        #pragma unroll
        for (int in = 0; in < 4; in++)
            #pragma unroll
            for (int r = 0; r < 4; r++) acc[im][in][r] = 0.f;

    #pragma unroll 1
    for (int t = 0; t < T; t++) {
        if (t == T - 1) { CP_WAIT(0); } else { CP_WAIT(1); }
        __syncthreads();
        uint32_t bA = sb + (uint32_t)(t & 1) * 24576u;
        uint32_t bB = bA + 16384u;

        #pragma unroll
        for (int ks = 0; ks < 4; ks++) {
            const int kb = ks * 32 + (lg >> 1) * 16;
            uint32_t a[2][4], b[2][4];
            #pragma unroll
            for (int im = 0; im < 2; im++) {
                int row = wm + im * 16 + (lg & 1) * 8 + lr;
                ldmatrix_x4(a[im], bA + SWZ128((uint32_t)(row * 128 + kb)));
            }
            #pragma unroll
            for (int ib = 0; ib < 2; ib++) {
                int row = wn + ib * 16 + (lg & 1) * 8 + lr;
                ldmatrix_x4(b[ib], bB + SWZ128((uint32_t)(row * 128 + kb)));
            }
            #pragma unroll
            for (int im = 0; im < 2; im++)
                #pragma unroll
                for (int in = 0; in < 4; in++) {
                    int ib = in >> 1, hi = in & 1;
                    mma16816(acc[im][in], a[im], b[ib][hi], b[ib][2 + hi]);
                }
        }
        __syncthreads();
        if (t + 2 <= T - 1) load_chunk(t & 1);
    }

    // ---------------- epilogue ----------------
    #pragma unroll
    for (int im = 0; im < 2; im++)
        #pragma unroll
        for (int half = 0; half < 2; half++) {
            int m = wm + im * 16 + (lane >> 2) + half * 8;   // local m
            #pragma unroll
            for (int in = 0; in < 4; in++) {
                int n = wn + in * 8 + (lane & 3) * 2;        // local n (even)
                float v0 = acc[im][in][half * 2 + 0];
                float v1 = acc[im][in][half * 2 + 1];

                if (EPI == 0) {
                    *(float2*)(Cf + (size_t)z * sC + (size_t)(m0 + m) * ldc + n0 + n) =
                        make_float2(v0, v1);
                } else if (EPI == 5) {
                    __nv_bfloat162 p;
                    p.x = __float2bfloat16(v0); p.y = __float2bfloat16(v1);
                    *(__nv_bfloat162*)(Chi + (size_t)z * sC + (size_t)(m0 + m) * ldc + n0 + n) = p;
                } else if (EPI == 1 || EPI == 2) {
                    int e = n0 + n, mg = m0 + m;
                    v0 = (v0 + bias[e]) * alpha;
                    v1 = (v1 + bias[e + 1]) * alpha;
                    int b = mg >> 10, s = mg & 1023, h = e >> 6, d = e & 63;
                    __nv_bfloat16 h0, l0, h1, l1;
                    split1(v0, h0, l0); split1(v1, h1, l1);
                    if (EPI == 1) {
                        size_t idx = (((size_t)(b * NH + h)) * SQ + s) * DH + d;
                        __nv_bfloat162 hp; hp.x = h0; hp.y = h1;
                        __nv_bfloat162 lp; lp.x = l0; lp.y = l1;
                        *(__nv_bfloat162*)(Chi + idx) = hp;
                        *(__nv_bfloat162*)(Clo + idx) = lp;
                    } else {
                        size_t base = (((size_t)(b * NH + h)) * DH + d) * SQ + s;
                        Chi[base] = h0;      Clo[base] = l0;
                        Chi[base + SQ] = h1; Clo[base + SQ] = l1;
                    }
                } else if (EPI == 3) {
                    int b = z / NH, h = z - b * NH;
                    int p = m0 + m;
                    size_t idx = ((size_t)(b * SQ + p)) * EMB + h * DH + (n0 + n);
                    __nv_bfloat16 h0, l0, h1, l1;
                    split1(v0, h0, l0); split1(v1, h1, l1);
                    __nv_bfloat162 hp; hp.x = h0; hp.y = h1;
                    __nv_bfloat162 lp; lp.x = l0; lp.y = l1;
                    *(__nv_bfloat162*)(Chi + idx) = hp;
                    *(__nv_bfloat162*)(Clo + idx) = lp;
                } else {  // EPI == 4
                    int e = n0 + n;
                    *(float2*)(Cf + (size_t)(m0 + m) * EMB + e) =
                        make_float2(v0 + bias[e], v1 + bias[e + 1]);
                }
            }
        }
}

// =================================================================================
// fp32 -> (hi, lo) bf16 split, elementwise
// =================================================================================
__global__ void __launch_bounds__(256)
split_pair(const float* __restrict__ x, __nv_bfloat16* __restrict__ hi,
           __nv_bfloat16* __restrict__ lo, int n)
{
    int i = blockIdx.x * 256 + threadIdx.x;
    if (i * 4 >= n) return;
    float4 v = ((const float4*)x)[i];
    __nv_bfloat16 h0, l0, h1, l1, h2, l2, h3, l3;
    split1(v.x, h0, l0); split1(v.y, h1, l1);
    split1(v.z, h2, l2); split1(v.w, h3, l3);
    __nv_bfloat162 ha, hb, la, lb;
    ha.x = h0; ha.y = h1; hb.x = h2; hb.y = h3;
    la.x = l0; la.y = l1; lb.x = l2; lb.y = l3;
    ((__nv_bfloat162*)hi)[2 * i]     = ha;
    ((__nv_bfloat162*)hi)[2 * i + 1] = hb;
    ((__nv_bfloat162*)lo)[2 * i]     = la;
    ((__nv_bfloat162*)lo)[2 * i + 1] = lb;
}

// =================================================================================
// Row softmax over rows of length 1024, bf16 input.
// =================================================================================
__device__ __forceinline__ float4 softmax_core(float4 v, int t, float* red) {
    float m = fmaxf(fmaxf(v.x, v.y), fmaxf(v.z, v.w));
    #pragma unroll
    for (int o = 16; o; o >>= 1) m = fmaxf(m, __shfl_xor_sync(0xffffffffu, m, o));
    if ((t & 31) == 0) red[t >> 5] = m;
    __syncthreads();
    m = red[0];
    #pragma unroll
    for (int i = 1; i < 8; i++) m = fmaxf(m, red[i]);

    v.x = __expf(v.x - m); v.y = __expf(v.y - m);
    v.z = __expf(v.z - m); v.w = __expf(v.w - m);
    float s = v.x + v.y + v.z + v.w;
    #pragma unroll
    for (int o = 16; o; o >>= 1) s += __shfl_xor_sync(0xffffffffu, s, o);
    __syncthreads();
    if ((t & 31) == 0) red[t >> 5] = s;
    __syncthreads();
    s = red[0];
    #pragma unroll
    for (int i = 1; i < 8; i++) s += red[i];

    float inv = 1.0f / s;
    v.x *= inv; v.y *= inv; v.z *= inv; v.w *= inv;
    return v;
}

__device__ __forceinline__ float4 load_bf16x4(const __nv_bfloat16* p, int t) {
    __nv_bfloat162 r0 = ((const __nv_bfloat162*)p)[2 * t];
    __nv_bfloat162 r1 = ((const __nv_bfloat162*)p)[2 * t + 1];
    return make_float4(__bfloat162float(r0.x), __bfloat162float(r0.y),
                       __bfloat162float(r1.x), __bfloat162float(r1.y));
}

__global__ void __launch_bounds__(256)
softmax_b16_to_b16(const __nv_bfloat16* __restrict__ in, __nv_bfloat16* __restrict__ out)
{
    const __nv_bfloat16* rowp = in + (size_t)blockIdx.x * 1024;
    __nv_bfloat16* orow = out + (size_t)blockIdx.x * 1024;
    const int t = threadIdx.x;
    __shared__ float red[8];
    float4 v = load_bf16x4(rowp, t);
    v = softmax_core(v, t, red);
    __nv_bfloat162 p0, p1;
    p0.x = __float2bfloat16(v.x); p0.y = __float2bfloat16(v.y);
    p1.x = __float2bfloat16(v.z); p1.y = __float2bfloat16(v.w);
    ((__nv_bfloat162*)orow)[2 * t]     = p0;
    ((__nv_bfloat162*)orow)[2 * t + 1] = p1;
}

__global__ void __launch_bounds__(256)
softmax_b16_to_split(const __nv_bfloat16* __restrict__ in, __nv_bfloat16* __restrict__ hi,
                     __nv_bfloat16* __restrict__ lo)
{
    const __nv_bfloat16* rowp = in + (size_t)blockIdx.x * 1024;
    __nv_bfloat16* hrow = hi + (size_t)blockIdx.x * 1024;
    __nv_bfloat16* lrow = lo + (size_t)blockIdx.x * 1024;
    const int t = threadIdx.x;
    __shared__ float red[8];
    float4 v = load_bf16x4(rowp, t);
    v = softmax_core(v, t, red);
    __nv_bfloat16 h0, l0, h1, l1, h2, l2, h3, l3;
    split1(v.x, h0, l0); split1(v.y, h1, l1);
    split1(v.z, h2, l2); split1(v.w, h3, l3);
    __nv_bfloat162 ha, hb, la, lb;
    ha.x = h0; ha.y = h1; hb.x = h2; hb.y = h3;
    la.x = l0; la.y = l1; lb.x = l2; lb.y = l3;
    ((__nv_bfloat162*)hrow)[2 * t]     = ha;
    ((__nv_bfloat162*)hrow)[2 * t + 1] = hb;
    ((__nv_bfloat162*)lrow)[2 * t]     = la;
    ((__nv_bfloat162*)lrow)[2 * t + 1] = lb;
}

// =================================================================================
extern "C" void kernel_launch(void* const* d_in, const int* in_sizes, int n_in,
                              void* d_out, int out_size)
{
    const float* l    = (const float*)d_in[0];
    const float* sp   = (const float*)d_in[1];
    const float* pp   = (const float*)d_in[2];
    const float* Wq   = (const float*)d_in[3];
    const float* bq   = (const float*)d_in[4];
    const float* Wksp = (const float*)d_in[5];
    const float* bksp = (const float*)d_in[6];
    const float* Wkp  = (const float*)d_in[7];
    const float* bkp  = (const float*)d_in[8];
    const float* Wvsp = (const float*)d_in[9];
    const float* bvsp = (const float*)d_in[10];
    const float* Wo   = (const float*)d_in[13];
    const float* bo   = (const float*)d_in[14];
    float* out = (float*)d_out;

    __nv_bfloat16 *lh, *ll, *sph, *spl, *pph, *ppl, *Wh, *Wl;
    __nv_bfloat16 *qh, *ql, *ksph, *kspl, *kph, *kpl, *vTh, *vTl;
    __nv_bfloat16 *A1r, *A2r, *A1h, *A2h, *SPr, *SPh, *SPl, *ctxh, *ctxl;
    cudaGetSymbolAddress((void**)&lh,  g_lh);   cudaGetSymbolAddress((void**)&ll,  g_ll);
    cudaGetSymbolAddress((void**)&sph, g_sph);  cudaGetSymbolAddress((void**)&spl, g_spl);
    cudaGetSymbolAddress((void**)&pph, g_pph);  cudaGetSymbolAddress((void**)&ppl, g_ppl);
    cudaGetSymbolAddress((void**)&Wh,  g_Wh);   cudaGetSymbolAddress((void**)&Wl,  g_Wl);
    cudaGetSymbolAddress((void**)&qh,  g_qh);   cudaGetSymbolAddress((void**)&ql,  g_ql);
    cudaGetSymbolAddress((void**)&ksph, g_ksph); cudaGetSymbolAddress((void**)&kspl, g_kspl);
    cudaGetSymbolAddress((void**)&kph, g_kph);  cudaGetSymbolAddress((void**)&kpl, g_kpl);
    cudaGetSymbolAddress((void**)&vTh, g_vTh);  cudaGetSymbolAddress((void**)&vTl, g_vTl);
    cudaGetSymbolAddress((void**)&A1r, g_A1r);  cudaGetSymbolAddress((void**)&A2r, g_A2r);
    cudaGetSymbolAddress((void**)&A1h, g_A1h);  cudaGetSymbolAddress((void**)&A2h, g_A2h);
    cudaGetSymbolAddress((void**)&SPr, g_SPr);
    cudaGetSymbolAddress((void**)&SPh, g_SPh);  cudaGetSymbolAddress((void**)&SPl, g_SPl);
    cudaGetSymbolAddress((void**)&ctxh, g_ctxh); cudaGetSymbolAddress((void**)&ctxl, g_ctxl);

    const float scale = 0.125f;  // 64^-0.5
    const size_t sHead = (size_t)SQ * DH;    // 65536
    const size_t sMat  = (size_t)SQ * SQ;    // 1048576

    // ---- split inputs to (hi, lo) bf16 ----
    split_pair<<<ACT_N / 1024, 256>>>(l,  lh,  ll,  ACT_N);
    split_pair<<<ACT_N / 1024, 256>>>(sp, sph, spl, ACT_N);
    split_pair<<<ACT_N / 1024, 256>>>(pp, pph, ppl, ACT_N);
    split_pair<<<WN / 1024, 256>>>(Wq,   Wh + 0 * WN, Wl + 0 * WN, WN);
    split_pair<<<WN / 1024, 256>>>(Wksp, Wh + 1 * WN, Wl + 1 * WN, WN);
    split_pair<<<WN / 1024, 256>>>(Wkp,  Wh + 2 * WN, Wl + 2 * WN, WN);
    split_pair<<<WN / 1024, 256>>>(Wvsp, Wh + 3 * WN, Wl + 3 * WN, WN);
    split_pair<<<WN / 1024, 256>>>(Wo,   Wh + 4 * WN, Wl + 4 * WN, WN);

    // ---- projections ----
    // q/ksp/kp: 2-segment (feed softmax only; 2^-9 relative error tolerable)
    // vsp: 3-segment (propagates linearly to output)
    dim3 gProj(EMB / 64, (NB * SQ) / 128, 1);   // (12, 64)
    gemm_bf16nt<1><<<gProj, 256>>>(lh,  ll,  ll,  Wh + 0*WN, Wh + 0*WN, Wh + 0*WN,
                                   2, EMB, 0, 0, nullptr, qh,  ql,  bq,   scale, 0, 0);
    gemm_bf16nt<1><<<gProj, 256>>>(sph, spl, spl, Wh + 1*WN, Wh + 1*WN, Wh + 1*WN,
                                   2, EMB, 0, 0, nullptr, ksph, kspl, bksp, scale, 0, 0);
    gemm_bf16nt<1><<<gProj, 256>>>(pph, ppl, ppl, Wh + 2*WN, Wh + 2*WN, Wh + 2*WN,
                                   2, EMB, 0, 0, nullptr, kph, kpl, bkp,  scale, 0, 0);
    gemm_bf16nt<2><<<gProj, 256>>>(sph, spl, sph, Wh + 3*WN, Wh + 3*WN, Wl + 3*WN,
                                   3, EMB, 0, 0, nullptr, vTh, vTl, bvsp, scale, 0, 0);

    // ---- transposed logits (2-segment, bf16 store): A1[k,s]=ksp_k.q_s ; A2[p,s]=kp_p.q_s
    dim3 gLog(SQ / 64, SQ / 128, BHC);          // (16, 8, 96)
    gemm_bf16nt<5><<<gLog, 256>>>(ksph, kspl, kspl, qh, qh, qh,
                                  2, DH, sHead, sHead, nullptr, A1r, nullptr, nullptr, 1.f, SQ, sMat);
    gemm_bf16nt<5><<<gLog, 256>>>(kph, kpl, kpl, qh, qh, qh,
                                  2, DH, sHead, sHead, nullptr, A2r, nullptr, nullptr, 1.f, SQ, sMat);

    // ---- softmax over s (row-wise), bf16 -> bf16 ----
    softmax_b16_to_b16<<<BHC * SQ, 256>>>(A1r, A1h);
    softmax_b16_to_b16<<<BHC * SQ, 256>>>(A2r, A2h);

    // ---- sp2p[p,k] = sum_s A2[p,s] * A1[k,s]  (single-segment bf16, bf16 store) ----
    gemm_bf16nt<5><<<gLog, 256>>>(A2h, A2h, A2h, A1h, A1h, A1h,
                                  1, SQ, sMat, sMat, nullptr, SPr, nullptr, nullptr, 1.f, SQ, sMat);

    // ---- softmax over k (row-wise) -> hi/lo split ----
    softmax_b16_to_split<<<BHC * SQ, 256>>>(SPr, SPh, SPl);

    // ---- ctx[b,p,h*64+d] = sum_k SP[p,k] * vsp[k,d]  (3-segment) ----
    dim3 gCtx(1, SQ / 128, BHC);                // (1, 8, 96)
    gemm_bf16nt<3><<<gCtx, 256>>>(SPh, SPl, SPh, vTh, vTh, vTl,
                                  3, SQ, sMat, sHead, nullptr, ctxh, ctxl, nullptr, 1.f, 0, 0);

    // ---- final: out = ctx @ Wo^T + bo  (3-segment) ----
    gemm_bf16nt<4><<<gProj, 256>>>(ctxh, ctxl, ctxh, Wh + 4*WN, Wh + 4*WN, Wl + 4*WN,
                                   3, EMB, 0, 0, out, nullptr, nullptr, bo, 1.f, 0, 0);
}

// round 13
// speedup vs baseline: 1.2366x; 1.0199x over previous
#include <cuda_runtime.h>
#include <cuda_bf16.h>
#include <cstdint>
#include <cstddef>

// Problem constants
#define NB 8
#define NH 12
#define SQ 1024
#define DH 64
#define EMB 768
#define BHC (NB*NH)      // 96
#define ACT_N (NB*SQ*EMB)   // 6291456
#define WN (EMB*EMB)        // 589824

// ---------------- scratch (static device globals; no allocation) ----------------
__device__ __nv_bfloat16 g_lh [ACT_N], g_ll [ACT_N];
__device__ __nv_bfloat16 g_sph[ACT_N], g_spl[ACT_N];
__device__ __nv_bfloat16 g_pph[ACT_N], g_ppl[ACT_N];
__device__ __nv_bfloat16 g_Wh [5*WN],  g_Wl [5*WN];     // Wq,Wksp,Wkp,Wvsp,Wo
__device__ __nv_bfloat16 g_qh  [ACT_N], g_ql  [ACT_N];
__device__ __nv_bfloat16 g_ksph[ACT_N], g_kspl[ACT_N];
__device__ __nv_bfloat16 g_kph [ACT_N], g_kpl [ACT_N];
__device__ __nv_bfloat16 g_vTh [ACT_N], g_vTl [ACT_N];  // [b,h,d,s]
__device__ __nv_bfloat16 g_A1r[100663296], g_A2r[100663296];   // raw logits (bf16)
__device__ __nv_bfloat16 g_A1h[100663296], g_A2h[100663296];   // softmaxed (bf16)
__device__ __nv_bfloat16 g_SPr[100663296];                      // raw sp2p (bf16)
__device__ __nv_bfloat16 g_SPh[100663296], g_SPl[100663296];   // softmaxed hi/lo
__device__ __nv_bfloat16 g_ctxh[ACT_N], g_ctxl[ACT_N];          // [b,p,e]

// =====================  helpers (baseline ISA only — no 'a' features) =====
__device__ __forceinline__ uint32_t smem_to_u32(const void* p) {
    uint32_t a;
    asm("{ .reg .u64 t; cvta.to.shared.u64 t, %1; cvt.u32.u64 %0, t; }" : "=r"(a) : "l"(p));
    return a;
}
__device__ __forceinline__ void cp_async16(uint32_t saddr, const void* gaddr) {
    asm volatile("cp.async.cg.shared.global [%0], [%1], 16;\n" :: "r"(saddr), "l"(gaddr));
}
#define CP_COMMIT()  asm volatile("cp.async.commit_group;\n" ::: "memory")
#define CP_WAIT(n)   asm volatile("cp.async.wait_group %0;\n" :: "n"(n) : "memory")
#define SWZ128(o) ((o) ^ (((o) >> 3) & 0x70))

__device__ __forceinline__ void ldmatrix_x4(uint32_t* r, uint32_t addr) {
    asm volatile("ldmatrix.sync.aligned.m8n8.x4.shared.b16 {%0,%1,%2,%3}, [%4];"
        : "=r"(r[0]), "=r"(r[1]), "=r"(r[2]), "=r"(r[3]) : "r"(addr));
}
__device__ __forceinline__ void mma16816(float* c, const uint32_t* a, uint32_t b0, uint32_t b1) {
    asm volatile("mma.sync.aligned.m16n8k16.row.col.f32.bf16.bf16.f32 "
        "{%0,%1,%2,%3}, {%4,%5,%6,%7}, {%8,%9}, {%0,%1,%2,%3};"
        : "+f"(c[0]), "+f"(c[1]), "+f"(c[2]), "+f"(c[3])
        : "r"(a[0]), "r"(a[1]), "r"(a[2]), "r"(a[3]), "r"(b0), "r"(b1));
}
__device__ __forceinline__ void split1(float v, __nv_bfloat16& h, __nv_bfloat16& l) {
    h = __float2bfloat16(v);
    l = __float2bfloat16(v - __bfloat162float(h));
}

// =================================================================================
// Unified bf16 NT GEMM (R10-proven core): C[m,n] = sum_seg sum_k Aseg[m,k]*Bseg[n,k].
// CTA tile 128(m) x 64(n), BK=64 (128B rows, SW128), double-buffered cp.async.
// 8 warps (4x2), warp tile 32x32, mma.sync m16n8k16 bf16 -> fp32 acc.
// Epilogues:
//  0: fp32 store  Cf[z*sC + m*ldc + n]
//  1: (acc+bias[e])*alpha -> hi/lo bf16 head layout [b,h,s,d]
//  2: same but transposed head layout [b,h,d,s]
//  3: acc -> hi/lo bf16 ctx layout [b, p, h*64+d]
//  4: acc+bias[n] -> fp32 out[m*EMB + n]
//  5: acc -> bf16 store Chi[z*sC + m*ldc + n]
// =================================================================================
template<int EPI>
__global__ void __launch_bounds__(256)
gemm_bf16nt(const __nv_bfloat16* __restrict__ A0, const __nv_bfloat16* __restrict__ A1p,
            const __nv_bfloat16* __restrict__ A2p,
            const __nv_bfloat16* __restrict__ B0, const __nv_bfloat16* __restrict__ B1p,
            const __nv_bfloat16* __restrict__ B2p,
            int nseg, int K, size_t sA, size_t sB,
            float* __restrict__ Cf, __nv_bfloat16* __restrict__ Chi,
            __nv_bfloat16* __restrict__ Clo,
            const float* __restrict__ bias, float alpha, int ldc, size_t sC)
{
    __shared__ __align__(1024) char smem_buf[49152];   // 2 x (16KB A + 8KB B)
    const uint32_t sb = smem_to_u32(smem_buf);
    const int tid = threadIdx.x, wid = tid >> 5, lane = tid & 31;
    const int z = blockIdx.z;
    const int m0 = blockIdx.y * 128, n0 = blockIdx.x * 64;
    const int cps = K >> 6;                  // 64-elem chunks per segment

    int l_seg = 0, l_kc = 0;                 // in-order load cursor
    auto load_chunk = [&](int buf) {
        const __nv_bfloat16* Ab = (l_seg == 0) ? A0 : ((l_seg == 1) ? A1p : A2p);
        const __nv_bfloat16* Bb = (l_seg == 0) ? B0 : ((l_seg == 1) ? B1p : B2p);
        Ab += (size_t)z * sA + (size_t)m0 * K + l_kc * 64;
        Bb += (size_t)z * sB + (size_t)n0 * K + l_kc * 64;
        uint32_t bA = sb + (uint32_t)buf * 24576u;
        uint32_t bB = bA + 16384u;
        #pragma unroll
        for (int i = 0; i < 4; i++) {                 // A: 128 rows x 8 x 16B
            int u = tid + i * 256, r = u >> 3, c = u & 7;
            cp_async16(bA + SWZ128((uint32_t)(r * 128 + c * 16)), Ab + (size_t)r * K + c * 8);
        }
        #pragma unroll
        for (int i = 0; i < 2; i++) {                 // B: 64 rows x 8 x 16B
            int u = tid + i * 256, r = u >> 3, c = u & 7;
            cp_async16(bB + SWZ128((uint32_t)(r * 128 + c * 16)), Bb + (size_t)r * K + c * 8);
        }
        CP_COMMIT();
        if (++l_kc == cps) { l_kc = 0; ++l_seg; }
    };

    const int T = nseg * cps;
    load_chunk(0);
    load_chunk(1);

    const int wm = (wid & 3) * 32;    // warp m offset
    const int wn = (wid >> 2) * 32;   // warp n offset
    const int lg = lane >> 3;
    const int lr = lane & 7;

    float acc[2][4][4];
    #pragma unroll
    for (int im = 0; im < 2; im++)
        #pragma unroll
        for (int in = 0; in < 4; in++)
            #pragma unroll
            for (int r = 0; r < 4; r++) acc[im][in][r] = 0.f;

    #pragma unroll 1
    for (int t = 0; t < T; t++) {
        if (t == T - 1) { CP_WAIT(0); } else { CP_WAIT(1); }
        __syncthreads();
        uint32_t bA = sb + (uint32_t)(t & 1) * 24576u;
        uint32_t bB = bA + 16384u;

        #pragma unroll
        for (int ks = 0; ks < 4; ks++) {
            const int kb = ks * 32 + (lg >> 1) * 16;
            uint32_t a[2][4], b[2][4];
            #pragma unroll
            for (int im = 0; im < 2; im++) {
                int row = wm + im * 16 + (lg & 1) * 8 + lr;
                ldmatrix_x4(a[im], bA + SWZ128((uint32_t)(row * 128 + kb)));
            }
            #pragma unroll
            for (int ib = 0; ib < 2; ib++) {
                int row = wn + ib * 16 + (lg & 1) * 8 + lr;
                ldmatrix_x4(b[ib], bB + SWZ128((uint32_t)(row * 128 + kb)));
            }
            #pragma unroll
            for (int im = 0; im < 2; im++)
                #pragma unroll
                for (int in = 0; in < 4; in++) {
                    int ib = in >> 1, hi = in & 1;
                    mma16816(acc[im][in], a[im], b[ib][hi], b[ib][2 + hi]);
                }
        }
        __syncthreads();
        if (t + 2 <= T - 1) load_chunk(t & 1);
    }

    // ---------------- epilogue ----------------
    #pragma unroll
    for (int im = 0; im < 2; im++)
        #pragma unroll
        for (int half = 0; half < 2; half++) {
            int m = wm + im * 16 + (lane >> 2) + half * 8;   // local m
            #pragma unroll
            for (int in = 0; in < 4; in++) {
                int n = wn + in * 8 + (lane & 3) * 2;        // local n (even)
                float v0 = acc[im][in][half * 2 + 0];
                float v1 = acc[im][in][half * 2 + 1];

                if (EPI == 0) {
                    *(float2*)(Cf + (size_t)z * sC + (size_t)(m0 + m) * ldc + n0 + n) =
                        make_float2(v0, v1);
                } else if (EPI == 5) {
                    __nv_bfloat162 p;
                    p.x = __float2bfloat16(v0); p.y = __float2bfloat16(v1);
                    *(__nv_bfloat162*)(Chi + (size_t)z * sC + (size_t)(m0 + m) * ldc + n0 + n) = p;
                } else if (EPI == 1 || EPI == 2) {
                    int e = n0 + n, mg = m0 + m;
                    v0 = (v0 + bias[e]) * alpha;
                    v1 = (v1 + bias[e + 1]) * alpha;
                    int b = mg >> 10, s = mg & 1023, h = e >> 6, d = e & 63;
                    __nv_bfloat16 h0, l0, h1, l1;
                    split1(v0, h0, l0); split1(v1, h1, l1);
                    if (EPI == 1) {
                        size_t idx = (((size_t)(b * NH + h)) * SQ + s) * DH + d;
                        __nv_bfloat162 hp; hp.x = h0; hp.y = h1;
                        __nv_bfloat162 lp; lp.x = l0; lp.y = l1;
                        *(__nv_bfloat162*)(Chi + idx) = hp;
                        *(__nv_bfloat162*)(Clo + idx) = lp;
                    } else {
                        size_t base = (((size_t)(b * NH + h)) * DH + d) * SQ + s;
                        Chi[base] = h0;      Clo[base] = l0;
                        Chi[base + SQ] = h1; Clo[base + SQ] = l1;
                    }
                } else if (EPI == 3) {
                    int b = z / NH, h = z - b * NH;
                    int p = m0 + m;
                    size_t idx = ((size_t)(b * SQ + p)) * EMB + h * DH + (n0 + n);
                    __nv_bfloat16 h0, l0, h1, l1;
                    split1(v0, h0, l0); split1(v1, h1, l1);
                    __nv_bfloat162 hp; hp.x = h0; hp.y = h1;
                    __nv_bfloat162 lp; lp.x = l0; lp.y = l1;
                    *(__nv_bfloat162*)(Chi + idx) = hp;
                    *(__nv_bfloat162*)(Clo + idx) = lp;
                } else {  // EPI == 4
                    int e = n0 + n;
                    *(float2*)(Cf + (size_t)(m0 + m) * EMB + e) =
                        make_float2(v0 + bias[e], v1 + bias[e + 1]);
                }
            }
        }
}

// =================================================================================
// sp2p-dedicated kernel: 128x128 CTA tile, SAME loop skeleton as gemm_bf16nt
// (BK=64, 128B rows, SWZ128, 2-stage). 8 warps as 2(m) x 4(n); warp tile 64x32.
// Single segment, K=SQ. Output: bf16 store to Chi[z*sMat + m*SQ + n].
// Dynamic smem: 2 x (16KB A + 16KB B) = 64KB.
// =================================================================================
__global__ void __launch_bounds__(256)
sp2p_mma128(const __nv_bfloat16* __restrict__ A, const __nv_bfloat16* __restrict__ B,
            __nv_bfloat16* __restrict__ C)
{
    extern __shared__ __align__(1024) char smem_dyn[];
    const uint32_t sb = smem_to_u32(smem_dyn);
    const int tid = threadIdx.x, wid = tid >> 5, lane = tid & 31;
    const int z = blockIdx.z;
    const int m0 = blockIdx.y * 128, n0 = blockIdx.x * 128;
    const size_t sMat = (size_t)SQ * SQ;

    const __nv_bfloat16* Ab0 = A + (size_t)z * sMat + (size_t)m0 * SQ;
    const __nv_bfloat16* Bb0 = B + (size_t)z * sMat + (size_t)n0 * SQ;

    auto load_chunk = [&](int kc, int buf) {
        uint32_t bA = sb + (uint32_t)buf * 32768u;
        uint32_t bB = bA + 16384u;
        const __nv_bfloat16* Ab = Ab0 + kc * 64;
        const __nv_bfloat16* Bb = Bb0 + kc * 64;
        #pragma unroll
        for (int i = 0; i < 4; i++) {                 // A: 128 rows x 8 x 16B
            int u = tid + i * 256, r = u >> 3, c = u & 7;
            cp_async16(bA + SWZ128((uint32_t)(r * 128 + c * 16)), Ab + (size_t)r * SQ + c * 8);
        }
        #pragma unroll
        for (int i = 0; i < 4; i++) {                 // B: 128 rows x 8 x 16B
            int u = tid + i * 256, r = u >> 3, c = u & 7;
            cp_async16(bB + SWZ128((uint32_t)(r * 128 + c * 16)), Bb + (size_t)r * SQ + c * 8);
        }
        CP_COMMIT();
    };

    load_chunk(0, 0);
    load_chunk(1, 1);

    const int wm = (wid & 1) * 64;    // warp m offset (0/64)
    const int wn = (wid >> 1) * 32;   // warp n offset (0..96)
    const int lg = lane >> 3;
    const int lr = lane & 7;

    float acc[4][4][4];
    #pragma unroll
    for (int im = 0; im < 4; im++)
        #pragma unroll
        for (int in = 0; in < 4; in++)
            #pragma unroll
            for (int r = 0; r < 4; r++) acc[im][in][r] = 0.f;

    const int T = SQ / 64;            // 16
    #pragma unroll 1
    for (int t = 0; t < T; t++) {
        if (t == T - 1) { CP_WAIT(0); } else { CP_WAIT(1); }
        __syncthreads();
        uint32_t bA = sb + (uint32_t)(t & 1) * 32768u;
        uint32_t bB = bA + 16384u;

        #pragma unroll
        for (int ks = 0; ks < 4; ks++) {
            const int kb = ks * 32 + (lg >> 1) * 16;
            uint32_t a[4][4], b[2][4];
            #pragma unroll
            for (int im = 0; im < 4; im++) {
                int row = wm + im * 16 + (lg & 1) * 8 + lr;
                ldmatrix_x4(a[im], bA + SWZ128((uint32_t)(row * 128 + kb)));
            }
            #pragma unroll
            for (int ib = 0; ib < 2; ib++) {
                int row = wn + ib * 16 + (lg & 1) * 8 + lr;
                ldmatrix_x4(b[ib], bB + SWZ128((uint32_t)(row * 128 + kb)));
            }
            #pragma unroll
            for (int im = 0; im < 4; im++)
                #pragma unroll
                for (int in = 0; in < 4; in++) {
                    int ib = in >> 1, hi = in & 1;
                    mma16816(acc[im][in], a[im], b[ib][hi], b[ib][2 + hi]);
                }
        }
        __syncthreads();
        if (t + 2 <= T - 1) load_chunk(t + 2, t & 1);
    }

    // epilogue: bf16 store
    __nv_bfloat16* Crow = C + (size_t)z * sMat;
    #pragma unroll
    for (int im = 0; im < 4; im++)
        #pragma unroll
        for (int half = 0; half < 2; half++) {
            int m = m0 + wm + im * 16 + (lane >> 2) + half * 8;
            #pragma unroll
            for (int in = 0; in < 4; in++) {
                int n = n0 + wn + in * 8 + (lane & 3) * 2;
                __nv_bfloat162 p;
                p.x = __float2bfloat16(acc[im][in][half * 2 + 0]);
                p.y = __float2bfloat16(acc[im][in][half * 2 + 1]);
                *(__nv_bfloat162*)(Crow + (size_t)m * SQ + n) = p;
            }
        }
}

// =================================================================================
// fp32 -> (hi, lo) bf16 split, elementwise
// =================================================================================
__global__ void __launch_bounds__(256)
split_pair(const float* __restrict__ x, __nv_bfloat16* __restrict__ hi,
           __nv_bfloat16* __restrict__ lo, int n)
{
    int i = blockIdx.x * 256 + threadIdx.x;
    if (i * 4 >= n) return;
    float4 v = ((const float4*)x)[i];
    __nv_bfloat16 h0, l0, h1, l1, h2, l2, h3, l3;
    split1(v.x, h0, l0); split1(v.y, h1, l1);
    split1(v.z, h2, l2); split1(v.w, h3, l3);
    __nv_bfloat162 ha, hb, la, lb;
    ha.x = h0; ha.y = h1; hb.x = h2; hb.y = h3;
    la.x = l0; la.y = l1; lb.x = l2; lb.y = l3;
    ((__nv_bfloat162*)hi)[2 * i]     = ha;
    ((__nv_bfloat162*)hi)[2 * i + 1] = hb;
    ((__nv_bfloat162*)lo)[2 * i]     = la;
    ((__nv_bfloat162*)lo)[2 * i + 1] = lb;
}

// =================================================================================
// Row softmax over rows of length 1024, bf16 input.
// =================================================================================
__device__ __forceinline__ float4 softmax_core(float4 v, int t, float* red) {
    float m = fmaxf(fmaxf(v.x, v.y), fmaxf(v.z, v.w));
    #pragma unroll
    for (int o = 16; o; o >>= 1) m = fmaxf(m, __shfl_xor_sync(0xffffffffu, m, o));
    if ((t & 31) == 0) red[t >> 5] = m;
    __syncthreads();
    m = red[0];
    #pragma unroll
    for (int i = 1; i < 8; i++) m = fmaxf(m, red[i]);

    v.x = __expf(v.x - m); v.y = __expf(v.y - m);
    v.z = __expf(v.z - m); v.w = __expf(v.w - m);
    float s = v.x + v.y + v.z + v.w;
    #pragma unroll
    for (int o = 16; o; o >>= 1) s += __shfl_xor_sync(0xffffffffu, s, o);
    __syncthreads();
    if ((t & 31) == 0) red[t >> 5] = s;
    __syncthreads();
    s = red[0];
    #pragma unroll
    for (int i = 1; i < 8; i++) s += red[i];

    float inv = 1.0f / s;
    v.x *= inv; v.y *= inv; v.z *= inv; v.w *= inv;
    return v;
}

__device__ __forceinline__ float4 load_bf16x4(const __nv_bfloat16* p, int t) {
    __nv_bfloat162 r0 = ((const __nv_bfloat162*)p)[2 * t];
    __nv_bfloat162 r1 = ((const __nv_bfloat162*)p)[2 * t + 1];
    return make_float4(__bfloat162float(r0.x), __bfloat162float(r0.y),
                       __bfloat162float(r1.x), __bfloat162float(r1.y));
}

__global__ void __launch_bounds__(256)
softmax_b16_to_b16(const __nv_bfloat16* __restrict__ in, __nv_bfloat16* __restrict__ out)
{
    const __nv_bfloat16* rowp = in + (size_t)blockIdx.x * 1024;
    __nv_bfloat16* orow = out + (size_t)blockIdx.x * 1024;
    const int t = threadIdx.x;
    __shared__ float red[8];
    float4 v = load_bf16x4(rowp, t);
    v = softmax_core(v, t, red);
    __nv_bfloat162 p0, p1;
    p0.x = __float2bfloat16(v.x); p0.y = __float2bfloat16(v.y);
    p1.x = __float2bfloat16(v.z); p1.y = __float2bfloat16(v.w);
    ((__nv_bfloat162*)orow)[2 * t]     = p0;
    ((__nv_bfloat162*)orow)[2 * t + 1] = p1;
}

__global__ void __launch_bounds__(256)
softmax_b16_to_split(const __nv_bfloat16* __restrict__ in, __nv_bfloat16* __restrict__ hi,
                     __nv_bfloat16* __restrict__ lo)
{
    const __nv_bfloat16* rowp = in + (size_t)blockIdx.x * 1024;
    __nv_bfloat16* hrow = hi + (size_t)blockIdx.x * 1024;
    __nv_bfloat16* lrow = lo + (size_t)blockIdx.x * 1024;
    const int t = threadIdx.x;
    __shared__ float red[8];
    float4 v = load_bf16x4(rowp, t);
    v = softmax_core(v, t, red);
    __nv_bfloat16 h0, l0, h1, l1, h2, l2, h3, l3;
    split1(v.x, h0, l0); split1(v.y, h1, l1);
    split1(v.z, h2, l2); split1(v.w, h3, l3);
    __nv_bfloat162 ha, hb, la, lb;
    ha.x = h0; ha.y = h1; hb.x = h2; hb.y = h3;
    la.x = l0; la.y = l1; lb.x = l2; lb.y = l3;
    ((__nv_bfloat162*)hrow)[2 * t]     = ha;
    ((__nv_bfloat162*)hrow)[2 * t + 1] = hb;
    ((__nv_bfloat162*)lrow)[2 * t]     = la;
    ((__nv_bfloat162*)lrow)[2 * t + 1] = lb;
}

// =================================================================================
extern "C" void kernel_launch(void* const* d_in, const int* in_sizes, int n_in,
                              void* d_out, int out_size)
{
    const float* l    = (const float*)d_in[0];
    const float* sp   = (const float*)d_in[1];
    const float* pp   = (const float*)d_in[2];
    const float* Wq   = (const float*)d_in[3];
    const float* bq   = (const float*)d_in[4];
    const float* Wksp = (const float*)d_in[5];
    const float* bksp = (const float*)d_in[6];
    const float* Wkp  = (const float*)d_in[7];
    const float* bkp  = (const float*)d_in[8];
    const float* Wvsp = (const float*)d_in[9];
    const float* bvsp = (const float*)d_in[10];
    const float* Wo   = (const float*)d_in[13];
    const float* bo   = (const float*)d_in[14];
    float* out = (float*)d_out;

    __nv_bfloat16 *lh, *ll, *sph, *spl, *pph, *ppl, *Wh, *Wl;
    __nv_bfloat16 *qh, *ql, *ksph, *kspl, *kph, *kpl, *vTh, *vTl;
    __nv_bfloat16 *A1r, *A2r, *A1h, *A2h, *SPr, *SPh, *SPl, *ctxh, *ctxl;
    cudaGetSymbolAddress((void**)&lh,  g_lh);   cudaGetSymbolAddress((void**)&ll,  g_ll);
    cudaGetSymbolAddress((void**)&sph, g_sph);  cudaGetSymbolAddress((void**)&spl, g_spl);
    cudaGetSymbolAddress((void**)&pph, g_pph);  cudaGetSymbolAddress((void**)&ppl, g_ppl);
    cudaGetSymbolAddress((void**)&Wh,  g_Wh);   cudaGetSymbolAddress((void**)&Wl,  g_Wl);
    cudaGetSymbolAddress((void**)&qh,  g_qh);   cudaGetSymbolAddress((void**)&ql,  g_ql);
    cudaGetSymbolAddress((void**)&ksph, g_ksph); cudaGetSymbolAddress((void**)&kspl, g_kspl);
    cudaGetSymbolAddress((void**)&kph, g_kph);  cudaGetSymbolAddress((void**)&kpl, g_kpl);
    cudaGetSymbolAddress((void**)&vTh, g_vTh);  cudaGetSymbolAddress((void**)&vTl, g_vTl);
    cudaGetSymbolAddress((void**)&A1r, g_A1r);  cudaGetSymbolAddress((void**)&A2r, g_A2r);
    cudaGetSymbolAddress((void**)&A1h, g_A1h);  cudaGetSymbolAddress((void**)&A2h, g_A2h);
    cudaGetSymbolAddress((void**)&SPr, g_SPr);
    cudaGetSymbolAddress((void**)&SPh, g_SPh);  cudaGetSymbolAddress((void**)&SPl, g_SPl);
    cudaGetSymbolAddress((void**)&ctxh, g_ctxh); cudaGetSymbolAddress((void**)&ctxl, g_ctxl);

    // Allow 64KB dynamic smem for the sp2p kernel (host attr call; not an allocation).
    cudaFuncSetAttribute(sp2p_mma128, cudaFuncAttributeMaxDynamicSharedMemorySize, 65536);

    const float scale = 0.125f;  // 64^-0.5
    const size_t sHead = (size_t)SQ * DH;    // 65536
    const size_t sMat  = (size_t)SQ * SQ;    // 1048576

    // ---- split inputs to (hi, lo) bf16 ----
    split_pair<<<ACT_N / 1024, 256>>>(l,  lh,  ll,  ACT_N);
    split_pair<<<ACT_N / 1024, 256>>>(sp, sph, spl, ACT_N);
    split_pair<<<ACT_N / 1024, 256>>>(pp, pph, ppl, ACT_N);
    split_pair<<<WN / 1024, 256>>>(Wq,   Wh + 0 * WN, Wl + 0 * WN, WN);
    split_pair<<<WN / 1024, 256>>>(Wksp, Wh + 1 * WN, Wl + 1 * WN, WN);
    split_pair<<<WN / 1024, 256>>>(Wkp,  Wh + 2 * WN, Wl + 2 * WN, WN);
    split_pair<<<WN / 1024, 256>>>(Wvsp, Wh + 3 * WN, Wl + 3 * WN, WN);
    split_pair<<<WN / 1024, 256>>>(Wo,   Wh + 4 * WN, Wl + 4 * WN, WN);

    // ---- projections ----
    dim3 gProj(EMB / 64, (NB * SQ) / 128, 1);   // (12, 64)
    gemm_bf16nt<1><<<gProj, 256>>>(lh,  ll,  ll,  Wh + 0*WN, Wh + 0*WN, Wh + 0*WN,
                                   2, EMB, 0, 0, nullptr, qh,  ql,  bq,   scale, 0, 0);
    gemm_bf16nt<1><<<gProj, 256>>>(sph, spl, spl, Wh + 1*WN, Wh + 1*WN, Wh + 1*WN,
                                   2, EMB, 0, 0, nullptr, ksph, kspl, bksp, scale, 0, 0);
    gemm_bf16nt<1><<<gProj, 256>>>(pph, ppl, ppl, Wh + 2*WN, Wh + 2*WN, Wh + 2*WN,
                                   2, EMB, 0, 0, nullptr, kph, kpl, bkp,  scale, 0, 0);
    gemm_bf16nt<2><<<gProj, 256>>>(sph, spl, sph, Wh + 3*WN, Wh + 3*WN, Wl + 3*WN,
                                   3, EMB, 0, 0, nullptr, vTh, vTl, bvsp, scale, 0, 0);

    // ---- transposed logits (2-segment, bf16 store) ----
    dim3 gLog(SQ / 64, SQ / 128, BHC);          // (16, 8, 96)
    gemm_bf16nt<5><<<gLog, 256>>>(ksph, kspl, kspl, qh, qh, qh,
                                  2, DH, sHead, sHead, nullptr, A1r, nullptr, nullptr, 1.f, SQ, sMat);
    gemm_bf16nt<5><<<gLog, 256>>>(kph, kpl, kpl, qh, qh, qh,
                                  2, DH, sHead, sHead, nullptr, A2r, nullptr, nullptr, 1.f, SQ, sMat);

    // ---- softmax over s (row-wise), bf16 -> bf16 ----
    softmax_b16_to_b16<<<BHC * SQ, 256>>>(A1r, A1h);
    softmax_b16_to_b16<<<BHC * SQ, 256>>>(A2r, A2h);

    // ---- sp2p[p,k] = sum_s A2[p,s] * A1[k,s]  (128x128-tile kernel, bf16 store) ----
    dim3 gSp(SQ / 128, SQ / 128, BHC);          // (8, 8, 96)
    sp2p_mma128<<<gSp, 256, 65536>>>(A2h, A1h, SPr);

    // ---- softmax over k (row-wise) -> hi/lo split ----
    softmax_b16_to_split<<<BHC * SQ, 256>>>(SPr, SPh, SPl);

    // ---- ctx[b,p,h*64+d] = sum_k SP[p,k] * vsp[k,d]  (3-segment) ----
    dim3 gCtx(1, SQ / 128, BHC);                // (1, 8, 96)
    gemm_bf16nt<3><<<gCtx, 256>>>(SPh, SPl, SPh, vTh, vTh, vTl,
                                  3, SQ, sMat, sHead, nullptr, ctxh, ctxl, nullptr, 1.f, 0, 0);

    // ---- final: out = ctx @ Wo^T + bo  (3-segment) ----
    gemm_bf16nt<4><<<gProj, 256>>>(ctxh, ctxl, ctxh, Wh + 4*WN, Wh + 4*WN, Wl + 4*WN,
                                   3, EMB, 0, 0, out, nullptr, nullptr, bo, 1.f, 0, 0);
}